// round 10
// baseline (speedup 1.0000x reference)
#include <cuda_runtime.h>

#define NQ 21
#define AD 18
#define NSTATE (1 << NQ)

typedef unsigned long long u64;

// 16MB statevector scratch, packed complex: low 32 bits = re, high = im.
static __device__ u64   g_psi[NSTATE];
static __device__ float g_z[NQ];
static __device__ float g_S;

// ---------- packed f32x2 helpers ----------

__device__ __forceinline__ u64 pack2(float lo, float hi) {
    u64 d; asm("mov.b64 %0, {%1,%2};" : "=l"(d) : "f"(lo), "f"(hi)); return d;
}
__device__ __forceinline__ void unpack2(u64 d, float& lo, float& hi) {
    asm("mov.b64 {%0,%1}, %2;" : "=f"(lo), "=f"(hi) : "l"(d));
}
__device__ __forceinline__ u64 dswap(u64 d) {
    float lo, hi; unpack2(d, lo, hi); return pack2(hi, lo);
}
__device__ __forceinline__ u64 ffma2(u64 a, u64 b, u64 c) {
    u64 d; asm("fma.rn.f32x2 %0, %1, %2, %3;" : "=l"(d) : "l"(a), "l"(b), "l"(c)); return d;
}
__device__ __forceinline__ u64 fmul2(u64 a, u64 b) {
    u64 d; asm("mul.rn.f32x2 %0, %1, %2;" : "=l"(d) : "l"(a), "l"(b)); return d;
}
__device__ __forceinline__ float2 cmulc(float2 a, float2 b) {
    return make_float2(a.x * b.x - a.y * b.y, a.x * b.y + a.y * b.x);
}

// U = RZ(g)*RY(b)*RX(a); packed coeffs (E.x,E.x), (-E.y,E.y) per element.
__device__ void compute_U(const float* p, u64* C) {
    float sx, cx, sy, cy, sz, cz;
    sincosf(0.5f * p[0], &sx, &cx);
    sincosf(0.5f * p[1], &sy, &cy);
    sincosf(0.5f * p[2], &sz, &cz);
    float2 m00 = make_float2( cy * cx,  sy * sx);
    float2 m01 = make_float2(-sy * cx, -cy * sx);
    float2 m10 = make_float2( sy * cx, -cy * sx);
    float2 m11 = make_float2( cy * cx, -sy * sx);
    float2 ezm = make_float2(cz, -sz), ezp = make_float2(cz, sz);
    float2 U0 = cmulc(ezm, m00), U1 = cmulc(ezm, m01);
    float2 U2 = cmulc(ezp, m10), U3 = cmulc(ezp, m11);
    C[0] = pack2(U0.x, U0.x); C[1] = pack2(-U0.y, U0.y);
    C[2] = pack2(U1.x, U1.x); C[3] = pack2(-U1.y, U1.y);
    C[4] = pack2(U2.x, U2.x); C[5] = pack2(-U2.y, U2.y);
    C[6] = pack2(U3.x, U3.x); C[7] = pack2(-U3.y, U3.y);
}

// Gate on register bit J (J in 0..2) within the 8-amp register file.
template<int J>
__device__ __forceinline__ void reg_gate(u64* a, const u64* C) {
    u64 c0 = C[0], c1 = C[1], c2 = C[2], c3 = C[3];
    u64 c4 = C[4], c5 = C[5], c6 = C[6], c7 = C[7];
#pragma unroll
    for (int r = 0; r < 8; ++r) {
        if (!(r & (1 << J))) {
            u64 x0 = a[r], x1 = a[r ^ (1 << J)];
            u64 s0 = dswap(x0), s1 = dswap(x1);
            a[r]            = ffma2(c0, x0, ffma2(c1, s0, ffma2(c2, x1, fmul2(c3, s1))));
            a[r ^ (1 << J)] = ffma2(c4, x0, ffma2(c5, s0, ffma2(c6, x1, fmul2(c7, s1))));
        }
    }
}

// Gate on lane bit k via shfl_xor.
__device__ __forceinline__ void lane_gate(u64* a, int l, int k, const u64* C) {
    int bit = (l >> k) & 1;
    u64 d0 = bit ? C[6] : C[0];
    u64 d1 = bit ? C[7] : C[1];
    u64 d2 = bit ? C[4] : C[2];
    u64 d3 = bit ? C[5] : C[3];
#pragma unroll
    for (int r = 0; r < 8; ++r) {
        u64 p = __shfl_xor_sync(0xffffffffu, a[r], 1 << k);
        a[r] = ffma2(d0, a[r], ffma2(d1, dswap(a[r]), ffma2(d2, p, fmul2(d3, dswap(p)))));
    }
}

__device__ __forceinline__ void wred(float v, float* dst) {
#pragma unroll
    for (int o = 16; o; o >>= 1) v += __shfl_down_sync(0xffffffffu, v, o);
    if ((threadIdx.x & 31) == 0) atomicAdd(dst, v);
}

// ---------- pass H': rotations wires 1..10 -------------------------------
// Tile bits: v0->g0 (passenger), v1..v4->g10..g13 (lanes), v5..v7->g14..g16,
// v8..v10->g17..g19. Chunk: c0..c8->g1..g9, c9->g20. No CNOT fold.
template<int FIRST>
__global__ void __launch_bounds__(256, 6) pass_hn(const float* __restrict__ params,
                                                  const float* __restrict__ state_in,
                                                  int layer) {
    __shared__ u64 s[2048];
    __shared__ u64 sC[NQ][8];
    int tid = threadIdx.x;
    int l = tid & 31, w = tid >> 5;   // w: 3 bits
    int c = blockIdx.x;               // 10 bits

    if (tid < NQ) compute_U(params + layer * 63 + tid * 3, sC[tid]);

    u64 a[8];
    // phase1: v = l | (w<<5) | (r<<8)  (lanes v0..4, warp v5..7, reg v8..10)
#pragma unroll
    for (int r = 0; r < 8; ++r) {
        int v = l | (w << 5) | (r << 8);
        int g = (v & 1) | ((c & 0x1FF) << 1) | (((v >> 1) & 0x3FF) << 10) | ((c >> 9) << 20);
        if (FIRST) a[r] = pack2(state_in[g], 0.0f);
        else       a[r] = g_psi[g];
    }
    __syncthreads();

    // lane bits v1..v4 -> g10..g13 -> wires 10,9,8,7
    lane_gate(a, l, 1, sC[10]);
    lane_gate(a, l, 2, sC[9]);
    lane_gate(a, l, 3, sC[8]);
    lane_gate(a, l, 4, sC[7]);
    // reg bits v8..v10 -> g17..g19 -> wires 3,2,1
    reg_gate<0>(a, sC[3]);
    reg_gate<1>(a, sC[2]);
    reg_gate<2>(a, sC[1]);

    // exchange warp(v5..7) <-> reg(v8..10)
#pragma unroll
    for (int r = 0; r < 8; ++r) s[l | (w << 5) | (r << 8)] = a[r];
    __syncthreads();
#pragma unroll
    for (int r = 0; r < 8; ++r) a[r] = s[l | (r << 5) | (w << 8)];

    // phase2: reg = v5..v7 -> g14..g16 -> wires 6,5,4
    reg_gate<0>(a, sC[6]);
    reg_gate<1>(a, sC[5]);
    reg_gate<2>(a, sC[4]);

#pragma unroll
    for (int r = 0; r < 8; ++r) {
        int v = l | (r << 5) | (w << 8);
        int g = (v & 1) | ((c & 0x1FF) << 1) | (((v >> 1) & 0x3FF) << 10) | ((c >> 9) << 20);
        g_psi[g] = a[r];
    }
}

// ---------- pass L': rotations wires 0, 11..20 ---------------------------
// Tile bits: v0..v4->g0..g4, v5..v7->g5..g7, v8->g8, v9->g9, v10->g20.
// Chunk: c0..c9 -> g10..g19.
// FOLD: entire CNOT ring folded into store address (layers 0..2).
// MEAS: layer 3 — no store, Z-measurement reduction instead.
template<int MEAS, int FOLD>
__global__ void __launch_bounds__(256, 6) pass_ln(const float* __restrict__ params, int layer) {
    __shared__ u64 s[2048];
    __shared__ u64 sC[NQ][8];
    __shared__ float red[22];
    int tid = threadIdx.x;
    int l = tid & 31, w = tid >> 5;
    int c = blockIdx.x;  // g10..g19

    if (tid < NQ) compute_U(params + layer * 63 + tid * 3, sC[tid]);
    if (MEAS && tid < 22) red[tid] = 0.f;

    u64 a[8];
#pragma unroll
    for (int r = 0; r < 8; ++r) {
        int v = l | (w << 5) | (r << 8);
        int g = (v & 0x3FF) | (c << 10) | ((v >> 10) << 20);
        a[r] = g_psi[g];
    }
    __syncthreads();

    // lane bits v0..v4 -> g0..g4 -> wires 20..16
    lane_gate(a, l, 0, sC[20]);
    lane_gate(a, l, 1, sC[19]);
    lane_gate(a, l, 2, sC[18]);
    lane_gate(a, l, 3, sC[17]);
    lane_gate(a, l, 4, sC[16]);
    // reg bits: v8->g8 (wire 12), v9->g9 (wire 11), v10->g20 (wire 0)
    reg_gate<0>(a, sC[12]);
    reg_gate<1>(a, sC[11]);
    reg_gate<2>(a, sC[0]);

    // exchange warp(v5..7) <-> reg(v8..10)
#pragma unroll
    for (int r = 0; r < 8; ++r) s[l | (w << 5) | (r << 8)] = a[r];
    __syncthreads();
#pragma unroll
    for (int r = 0; r < 8; ++r) a[r] = s[l | (r << 5) | (w << 8)];

    // phase2: reg = v5..v7 -> g5..g7 -> wires 15,14,13
    reg_gate<0>(a, sC[15]);
    reg_gate<1>(a, sC[14]);
    reg_gate<2>(a, sC[13]);

    if (FOLD) {
        // CNOT ring: y_b = XOR_{j=b..20} x_j (b<=19), y20 = XOR_{j=0..19} x_j
#pragma unroll
        for (int r = 0; r < 8; ++r) {
            int v = l | (r << 5) | (w << 8);
            int x = (v & 0x3FF) | (c << 10) | ((v >> 10) << 20);
            int sx = x;
            sx ^= sx >> 1; sx ^= sx >> 2; sx ^= sx >> 4; sx ^= sx >> 8; sx ^= sx >> 16;
            int y = (sx & 0xFFFFF) | (((sx ^ (x >> 20)) & 1) << 20);
            g_psi[y] = a[r];
        }
    }

    if (MEAS) {
        // phase2 layout: v = l | (r<<5) | (w<<8): lanes v0..4, reg v5..7, warp v8..10
        float S = 0.f, t5 = 0.f, t6 = 0.f, t7 = 0.f;
#pragma unroll
        for (int r = 0; r < 8; ++r) {
            float re, im; unpack2(a[r], re, im);
            float m = fmaf(re, re, im * im);
            S += m;
            t5 += (r & 1) ? -m : m;   // v5 = g5 -> wire 15
            t6 += (r & 2) ? -m : m;   // v6 = g6 -> wire 14
            t7 += (r & 4) ? -m : m;   // v7 = g7 -> wire 13
        }
        wred((l & 1)  ? -S : S, &red[20]);   // v0=g0 -> wire 20
        wred((l & 2)  ? -S : S, &red[19]);
        wred((l & 4)  ? -S : S, &red[18]);
        wred((l & 8)  ? -S : S, &red[17]);
        wred((l & 16) ? -S : S, &red[16]);
        wred(t5, &red[15]);
        wred(t6, &red[14]);
        wred(t7, &red[13]);
        wred((w & 1) ? -S : S, &red[12]);    // v8=g8 -> wire 12
        wred((w & 2) ? -S : S, &red[11]);    // v9=g9 -> wire 11
        wred((w & 4) ? -S : S, &red[0]);     // v10=g20 -> wire 0
        wred(S, &red[21]);
        __syncthreads();
        if (tid == 0) {
            atomicAdd(&g_S, red[21]);
            atomicAdd(&g_z[0], red[0]);
#pragma unroll
            for (int q = 11; q <= 20; ++q) atomicAdd(&g_z[q], red[q]);
        } else if (tid == 32) {
            // wires 1..10: bit g(20-q) = chunk bit c(10-q)
            float Sb = red[21];
#pragma unroll
            for (int q = 1; q <= 10; ++q)
                atomicAdd(&g_z[q], ((c >> (10 - q)) & 1) ? -Sb : Sb);
        }
    }
}

// ---------- tiny kernels ----------
__global__ void zero_acc() {
    int t = threadIdx.x;
    if (t < NQ) g_z[t] = 0.f;
    if (t == NQ) g_S = 0.f;
}

__global__ void head_kernel(const float* __restrict__ w, const float* __restrict__ b,
                            float* __restrict__ out) {
    if (threadIdx.x == 0) {
        float S = g_S;
        float inv = (S > 0.0f) ? (1.0f / S) : 0.0f;
        float meas[NQ];
        for (int q = 0; q < NQ; ++q) meas[q] = g_z[q] * inv;
        float logits[AD];
        float mx = -1e30f;
        for (int ai = 0; ai < AD; ++ai) {
            float t = b[ai];
            for (int q = 0; q < NQ; ++q) t = fmaf(w[ai * NQ + q], meas[q], t);
            logits[ai] = t;
            if (t > mx) mx = t;
        }
        float sum = 0.0f;
        for (int ai = 0; ai < AD; ++ai) {
            float e = expf(logits[ai] - mx);
            logits[ai] = e;
            sum += e;
        }
        float is = 1.0f / sum;
        for (int ai = 0; ai < AD; ++ai) out[ai] = logits[ai] * is;
    }
}

// ---------- launch ----------
extern "C" void kernel_launch(void* const* d_in, const int* in_sizes, int n_in,
                              void* d_out, int out_size) {
    const float* state  = (const float*)d_in[0];  // 2^21 float32
    const float* params = (const float*)d_in[1];  // 252 float32
    const float* hw     = (const float*)d_in[2];  // 18*21 float32
    const float* hb     = (const float*)d_in[3];  // 18 float32
    float* out = (float*)d_out;

    zero_acc<<<1, 32>>>();
    pass_hn<1><<<1024, 256>>>(params, state, 0);
    pass_ln<0, 1><<<1024, 256>>>(params, 0);
    pass_hn<0><<<1024, 256>>>(params, state, 1);
    pass_ln<0, 1><<<1024, 256>>>(params, 1);
    pass_hn<0><<<1024, 256>>>(params, state, 2);
    pass_ln<0, 1><<<1024, 256>>>(params, 2);
    pass_hn<0><<<1024, 256>>>(params, state, 3);
    pass_ln<1, 0><<<1024, 256>>>(params, 3);
    head_kernel<<<1, 32>>>(hw, hb, out);
}

// round 11
// speedup vs baseline: 1.3340x; 1.3340x over previous
#include <cuda_runtime.h>

#define NQ 21
#define AD 18
#define NSTATE (1 << NQ)

typedef unsigned long long u64;

// 16MB statevector scratch, stored as packed complex: low 32 bits = re, high = im.
static __device__ u64   g_psi[NSTATE];
static __device__ float g_zd[NQ];   // sum |psi|^2 * (+1 if bit=0 else -1) per wire
static __device__ float g_cr[NQ];   // Re sum psi(bit=0) conj(psi(bit=1))
static __device__ float g_ci[NQ];   // Im of same
static __device__ float g_S;

// ---------- packed f32x2 helpers ----------

__device__ __forceinline__ u64 pack2(float lo, float hi) {
    u64 d; asm("mov.b64 %0, {%1,%2};" : "=l"(d) : "f"(lo), "f"(hi)); return d;
}
__device__ __forceinline__ void unpack2(u64 d, float& lo, float& hi) {
    asm("mov.b64 {%0,%1}, %2;" : "=f"(lo), "=f"(hi) : "l"(d));
}
__device__ __forceinline__ u64 dswap(u64 d) {  // (re,im) -> (im,re)
    float lo, hi; unpack2(d, lo, hi); return pack2(hi, lo);
}
__device__ __forceinline__ u64 ffma2(u64 a, u64 b, u64 c) {
    u64 d; asm("fma.rn.f32x2 %0, %1, %2, %3;" : "=l"(d) : "l"(a), "l"(b), "l"(c)); return d;
}
__device__ __forceinline__ u64 fmul2(u64 a, u64 b) {
    u64 d; asm("mul.rn.f32x2 %0, %1, %2;" : "=l"(d) : "l"(a), "l"(b)); return d;
}

__device__ __forceinline__ float2 cmulc(float2 a, float2 b) {
    return make_float2(a.x * b.x - a.y * b.y, a.x * b.y + a.y * b.x);
}

// U = RZ(g)*RY(b)*RX(a); packed coeffs: for element E: (E.x,E.x), (-E.y,E.y).
__device__ void compute_U(const float* p, u64* C) {
    float sx, cx, sy, cy, sz, cz;
    sincosf(0.5f * p[0], &sx, &cx);
    sincosf(0.5f * p[1], &sy, &cy);
    sincosf(0.5f * p[2], &sz, &cz);
    float2 m00 = make_float2( cy * cx,  sy * sx);
    float2 m01 = make_float2(-sy * cx, -cy * sx);
    float2 m10 = make_float2( sy * cx, -cy * sx);
    float2 m11 = make_float2( cy * cx, -sy * sx);
    float2 ezm = make_float2(cz, -sz), ezp = make_float2(cz, sz);
    float2 U0 = cmulc(ezm, m00), U1 = cmulc(ezm, m01);
    float2 U2 = cmulc(ezp, m10), U3 = cmulc(ezp, m11);
    C[0] = pack2(U0.x, U0.x); C[1] = pack2(-U0.y, U0.y);
    C[2] = pack2(U1.x, U1.x); C[3] = pack2(-U1.y, U1.y);
    C[4] = pack2(U2.x, U2.x); C[5] = pack2(-U2.y, U2.y);
    C[6] = pack2(U3.x, U3.x); C[7] = pack2(-U3.y, U3.y);
}

// Gate on register bit J: pairs (r, r^(1<<J)) within the 16-amp register file.
template<int J>
__device__ __forceinline__ void reg_gate(u64* a, const u64* C) {
    u64 c0 = C[0], c1 = C[1], c2 = C[2], c3 = C[3];
    u64 c4 = C[4], c5 = C[5], c6 = C[6], c7 = C[7];
#pragma unroll
    for (int r = 0; r < 16; ++r) {
        if (!(r & (1 << J))) {
            u64 x0 = a[r], x1 = a[r ^ (1 << J)];
            u64 s0 = dswap(x0), s1 = dswap(x1);
            a[r]            = ffma2(c0, x0, ffma2(c1, s0, ffma2(c2, x1, fmul2(c3, s1))));
            a[r ^ (1 << J)] = ffma2(c4, x0, ffma2(c5, s0, ffma2(c6, x1, fmul2(c7, s1))));
        }
    }
}

// Gate on lane bit k via shfl_xor.
__device__ __forceinline__ void lane_gate(u64* a, int l, int k, const u64* C) {
    int bit = (l >> k) & 1;
    u64 d0 = bit ? C[6] : C[0];
    u64 d1 = bit ? C[7] : C[1];
    u64 d2 = bit ? C[4] : C[2];
    u64 d3 = bit ? C[5] : C[3];
#pragma unroll
    for (int r = 0; r < 16; ++r) {
        u64 p = __shfl_xor_sync(0xffffffffu, a[r], 1 << k);
        a[r] = ffma2(d0, a[r], ffma2(d1, dswap(a[r]), ffma2(d2, p, fmul2(d3, dswap(p)))));
    }
}

// ---------- pass H: local bits v0,v1 -> g0,g1 ; v2..v11 -> g11..g20 ----------
template<int FIRST, int DO_CNOT>
__global__ void __launch_bounds__(256, 4) pass_h(const float* __restrict__ params,
                                                 const float* __restrict__ state_in,
                                                 int layer) {
    __shared__ u64 s[4096];
    __shared__ u64 sC[NQ][8];
    int tid = threadIdx.x;
    int l = tid & 31, w = tid >> 5;
    int c = blockIdx.x;  // chunk = g2..g10

    if (FIRST && c == 0) {  // fold accumulator zeroing into layer-0 pass
        if (tid < NQ) { g_zd[tid] = 0.f; g_cr[tid] = 0.f; g_ci[tid] = 0.f; }
        if (tid == NQ) g_S = 0.f;
    }
    if (tid < NQ) compute_U(params + layer * 63 + tid * 3, sC[tid]);

    u64 a[16];
#pragma unroll
    for (int r = 0; r < 16; ++r) {
        int v = l | (r << 5) | (w << 9);
        int g = (v & 3) | (c << 2) | ((v >> 2) << 11);
        if (FIRST) a[r] = pack2(state_in[g], 0.0f);
        else       a[r] = g_psi[g];
    }
    __syncthreads();

    lane_gate(a, l, 2, sC[9]);
    lane_gate(a, l, 3, sC[8]);
    lane_gate(a, l, 4, sC[7]);
    reg_gate<0>(a, sC[6]);
    reg_gate<1>(a, sC[5]);
    reg_gate<2>(a, sC[4]);
    reg_gate<3>(a, sC[3]);

#pragma unroll
    for (int r = 0; r < 16; ++r) s[l | (r << 5) | (w << 9)] = a[r];
    __syncthreads();
#pragma unroll
    for (int r = 0; r < 16; ++r) a[r] = s[l | (w << 5) | (r << 8)];

    reg_gate<1>(a, sC[2]);
    reg_gate<2>(a, sC[1]);
    reg_gate<3>(a, sC[0]);

#pragma unroll
    for (int r = 0; r < 16; ++r) {
        int v = l | (w << 5) | (r << 8);
        int wv = v;
        if (DO_CNOT) {
            int x = v;
            x ^= x >> 1; x ^= x >> 2; x ^= x >> 4; x ^= x >> 8;
            wv = (v & ~0x7FC) | (x & 0x7FC);
        }
        int g = (wv & 3) | (c << 2) | ((wv >> 2) << 11);
        g_psi[g] = a[r];
    }
}

// ---------- pass L: local bits v0..v10 -> g0..g10 ; v11 -> g20 ----------
__global__ void __launch_bounds__(256, 4) pass_l(const float* __restrict__ params, int layer) {
    __shared__ u64 s[4096];
    __shared__ u64 sC[NQ][8];
    int tid = threadIdx.x;
    int l = tid & 31, w = tid >> 5;
    int c = blockIdx.x;  // chunk = g11..g19

    if (tid < NQ) compute_U(params + layer * 63 + tid * 3, sC[tid]);

    u64 a[16];
#pragma unroll
    for (int r = 0; r < 16; ++r) {
        int v = l | (r << 5) | (w << 9);
        int g = (v & 0x7FF) | (c << 11) | ((v >> 11) << 20);
        a[r] = g_psi[g];
    }
    __syncthreads();

    lane_gate(a, l, 0, sC[20]);
    lane_gate(a, l, 1, sC[19]);
    lane_gate(a, l, 2, sC[18]);
    lane_gate(a, l, 3, sC[17]);
    lane_gate(a, l, 4, sC[16]);
    reg_gate<0>(a, sC[15]);
    reg_gate<1>(a, sC[14]);
    reg_gate<2>(a, sC[13]);
    reg_gate<3>(a, sC[12]);

#pragma unroll
    for (int r = 0; r < 16; ++r) s[l | (r << 5) | (w << 9)] = a[r];
    __syncthreads();
#pragma unroll
    for (int r = 0; r < 16; ++r) a[r] = s[l | (w << 5) | (r << 8)];

    reg_gate<1>(a, sC[11]);
    reg_gate<2>(a, sC[10]);

    int K = (c & 1) ? 0x7FF : 0;
#pragma unroll
    for (int r = 0; r < 16; ++r) {
        int v = l | (w << 5) | (r << 8);
        int u = v & 0x7FF;
        int x = u;
        x ^= x >> 1; x ^= x >> 2; x ^= x >> 4; x ^= x >> 8;
        int low = x ^ K;
        int wv = low | ((((v >> 11) ^ low) & 1) << 11);
        int g = (wv & 0x7FF) | (c << 11) | ((wv >> 11) << 20);
        g_psi[g] = a[r];
    }
}

// ---------- measurement reductions ----------
// After layer 2 (state in g_psi), layer 3 = 21 commuting 1-qubit rotations then
// Z measurement. Z'_q = M00*(d0-d1) + 2 Re(c_q * M10) with M = U_q^dag Z U_q,
// c_q = sum psi(bit=0) conj(psi(bit=1)). Only (zd, c) reductions needed here.

__device__ __forceinline__ void wred(float v, float* dst) {
#pragma unroll
    for (int o = 16; o; o >>= 1) v += __shfl_down_sync(0xffffffffu, v, o);
    if ((threadIdx.x & 31) == 0) atomicAdd(dst, v);
}

__device__ __forceinline__ void lane_c(const float2* A, int l, int k, float sk,
                                       float* red_re, float* red_im) {
    float cre = 0.f, cim = 0.f;
#pragma unroll
    for (int r = 0; r < 16; ++r) {
        float pr = __shfl_xor_sync(0xffffffffu, A[r].x, 1 << k);
        float pi = __shfl_xor_sync(0xffffffffu, A[r].y, 1 << k);
        float tre = fmaf(A[r].x, pr, A[r].y * pi);
        float tim = fmaf(A[r].y, pr, -A[r].x * pi);
        cre += tre;
        cim = fmaf(sk, tim, cim);
    }
    wred(0.5f * cre, red_re);
    wred(0.5f * cim, red_im);
}

template<int J>
__device__ __forceinline__ void reg_c(const float2* A, float* red_re, float* red_im) {
    float cre = 0.f, cim = 0.f;
#pragma unroll
    for (int r = 0; r < 16; ++r) {
        if (!(r & (1 << J))) {
            float2 x0 = A[r], x1 = A[r ^ (1 << J)];
            cre = fmaf(x0.x, x1.x, fmaf(x0.y, x1.y, cre));
            cim = fmaf(x0.y, x1.x, fmaf(-x0.x, x1.y, cim));
        }
    }
    wred(cre, red_re);
    wred(cim, red_im);
}

// ---------- meas_hl: merged H-tiling (blocks 0..511) + L-tiling (512..1023) --
__global__ void __launch_bounds__(256, 4) meas_hl() {
    __shared__ float2 s[4096];
    __shared__ float red[33];
    int tid = threadIdx.x;
    int l = tid & 31, w = tid >> 5;
    const float2* ps = (const float2*)g_psi;

    if (tid < 33) red[tid] = 0.f;
    __syncthreads();

    if (blockIdx.x < 512) {
        // ===== H tiling: measures wires 0..9 (bits g11..g20) + S =====
        // red layout: [0..9]=zd wires0..9, [10]=S, [11..20]=cre, [21..30]=cim
        int c = blockIdx.x;
        float2 A[16];
#pragma unroll
        for (int r = 0; r < 16; ++r) {
            int v = l | (r << 5) | (w << 9);
            int g = (v & 3) | (c << 2) | ((v >> 2) << 11);
            A[r] = ps[g];
        }

        float S = 0.f, z5 = 0.f, z6 = 0.f, z7 = 0.f, z8 = 0.f;
#pragma unroll
        for (int r = 0; r < 16; ++r) {
            float m = fmaf(A[r].x, A[r].x, A[r].y * A[r].y);
            S += m;
            z5 += (r & 1) ? -m : m;
            z6 += (r & 2) ? -m : m;
            z7 += (r & 4) ? -m : m;
            z8 += (r & 8) ? -m : m;
        }
        float s2 = (l & 4)  ? -1.f : 1.f;
        float s3 = (l & 8)  ? -1.f : 1.f;
        float s4 = (l & 16) ? -1.f : 1.f;
        wred(s2 * S, &red[9]);   // v2 -> wire 9
        wred(s3 * S, &red[8]);
        wred(s4 * S, &red[7]);
        wred(z5, &red[6]);
        wred(z6, &red[5]);
        wred(z7, &red[4]);
        wred(z8, &red[3]);
        wred(((w & 1) ? -S : S), &red[2]);  // v9 -> wire 2
        wred(((w & 2) ? -S : S), &red[1]);
        wred(((w & 4) ? -S : S), &red[0]);
        wred(S, &red[10]);

        lane_c(A, l, 2, s2, &red[11 + 9], &red[21 + 9]);
        lane_c(A, l, 3, s3, &red[11 + 8], &red[21 + 8]);
        lane_c(A, l, 4, s4, &red[11 + 7], &red[21 + 7]);
        reg_c<0>(A, &red[11 + 6], &red[21 + 6]);
        reg_c<1>(A, &red[11 + 5], &red[21 + 5]);
        reg_c<2>(A, &red[11 + 4], &red[21 + 4]);

#pragma unroll
        for (int r = 0; r < 16; ++r) s[l | (r << 5) | (w << 9)] = A[r];
        __syncthreads();
#pragma unroll
        for (int r = 0; r < 16; ++r) A[r] = s[l | (w << 5) | (r << 8)];

        reg_c<0>(A, &red[11 + 3], &red[21 + 3]);
        reg_c<1>(A, &red[11 + 2], &red[21 + 2]);
        reg_c<2>(A, &red[11 + 1], &red[21 + 1]);
        reg_c<3>(A, &red[11 + 0], &red[21 + 0]);

        __syncthreads();
        if (tid < 10) {
            atomicAdd(&g_zd[tid], red[tid]);
            atomicAdd(&g_cr[tid], red[11 + tid]);
            atomicAdd(&g_ci[tid], red[21 + tid]);
        }
        if (tid == 10) atomicAdd(&g_S, red[10]);
    } else {
        // ===== L tiling: measures wires 10..20 (bits g0..g10) =====
        // red layout: [0..10]=zd wires10..20 (idx=wire-10), [11..21]=cre, [22..32]=cim
        int c = blockIdx.x - 512;
        float2 A[16];
#pragma unroll
        for (int r = 0; r < 16; ++r) {
            int v = l | (r << 5) | (w << 9);
            int g = (v & 0x7FF) | (c << 11) | ((v >> 11) << 20);
            A[r] = ps[g];
        }

        float S = 0.f, z5 = 0.f, z6 = 0.f, z7 = 0.f, z8 = 0.f;
#pragma unroll
        for (int r = 0; r < 16; ++r) {
            float m = fmaf(A[r].x, A[r].x, A[r].y * A[r].y);
            S += m;
            z5 += (r & 1) ? -m : m;
            z6 += (r & 2) ? -m : m;
            z7 += (r & 4) ? -m : m;
            z8 += (r & 8) ? -m : m;
        }
        float s0 = (l & 1)  ? -1.f : 1.f;
        float s1 = (l & 2)  ? -1.f : 1.f;
        float s2 = (l & 4)  ? -1.f : 1.f;
        float s3 = (l & 8)  ? -1.f : 1.f;
        float s4 = (l & 16) ? -1.f : 1.f;
        wred(s0 * S, &red[20 - 10]);  // v0 -> wire 20
        wred(s1 * S, &red[19 - 10]);
        wred(s2 * S, &red[18 - 10]);
        wred(s3 * S, &red[17 - 10]);
        wred(s4 * S, &red[16 - 10]);
        wred(z5, &red[15 - 10]);
        wred(z6, &red[14 - 10]);
        wred(z7, &red[13 - 10]);
        wred(z8, &red[12 - 10]);
        wred(((w & 1) ? -S : S), &red[11 - 10]);  // v9 -> wire 11
        wred(((w & 2) ? -S : S), &red[10 - 10]);  // v10 -> wire 10

        lane_c(A, l, 0, s0, &red[11 + 10], &red[22 + 10]);
        lane_c(A, l, 1, s1, &red[11 + 9],  &red[22 + 9]);
        lane_c(A, l, 2, s2, &red[11 + 8],  &red[22 + 8]);
        lane_c(A, l, 3, s3, &red[11 + 7],  &red[22 + 7]);
        lane_c(A, l, 4, s4, &red[11 + 6],  &red[22 + 6]);
        reg_c<0>(A, &red[11 + 5], &red[22 + 5]);
        reg_c<1>(A, &red[11 + 4], &red[22 + 4]);
        reg_c<2>(A, &red[11 + 3], &red[22 + 3]);

#pragma unroll
        for (int r = 0; r < 16; ++r) s[l | (r << 5) | (w << 9)] = A[r];
        __syncthreads();
#pragma unroll
        for (int r = 0; r < 16; ++r) A[r] = s[l | (w << 5) | (r << 8)];

        reg_c<0>(A, &red[11 + 2], &red[22 + 2]);
        reg_c<1>(A, &red[11 + 1], &red[22 + 1]);
        reg_c<2>(A, &red[11 + 0], &red[22 + 0]);

        __syncthreads();
        if (tid < 11) {
            atomicAdd(&g_zd[10 + tid], red[tid]);
            atomicAdd(&g_cr[10 + tid], red[11 + tid]);
            atomicAdd(&g_ci[10 + tid], red[22 + tid]);
        }
    }
}

// ---------- head ----------
__global__ void head_kernel(const float* __restrict__ params,
                            const float* __restrict__ w, const float* __restrict__ b,
                            float* __restrict__ out) {
    __shared__ float smeas[NQ];
    __shared__ float slog[AD];
    int t = threadIdx.x;
    float S = g_S;
    float inv = (S > 0.0f) ? (1.0f / S) : 0.0f;
    if (t < NQ) {
        const float* p = params + 3 * 63 + t * 3;
        float sx, cx, sy, cy, sz, cz;
        sincosf(0.5f * p[0], &sx, &cx);
        sincosf(0.5f * p[1], &sy, &cy);
        sincosf(0.5f * p[2], &sz, &cz);
        float2 m00 = make_float2( cy * cx,  sy * sx);
        float2 m01 = make_float2(-sy * cx, -cy * sx);
        float2 m10 = make_float2( sy * cx, -cy * sx);
        float2 m11 = make_float2( cy * cx, -sy * sx);
        float2 ezm = make_float2(cz, -sz), ezp = make_float2(cz, sz);
        float2 a = cmulc(ezm, m00);   // u00
        float2 bb = cmulc(ezm, m01);  // u01
        float2 cc = cmulc(ezp, m10);  // u10
        float2 d = cmulc(ezp, m11);   // u11
        float M00 = (a.x * a.x + a.y * a.y) - (cc.x * cc.x + cc.y * cc.y);
        float M10r = (bb.x * a.x + bb.y * a.y) - (d.x * cc.x + d.y * cc.y);
        float M10i = (bb.x * a.y - bb.y * a.x) - (d.x * cc.y - d.y * cc.x);
        smeas[t] = (M00 * g_zd[t] + 2.0f * (M10r * g_cr[t] - M10i * g_ci[t])) * inv;
    }
    __syncthreads();
    if (t < AD) {
        float acc = b[t];
#pragma unroll
        for (int q = 0; q < NQ; ++q) acc = fmaf(w[t * NQ + q], smeas[q], acc);
        slog[t] = acc;
    }
    __syncthreads();
    if (t == 0) {
        float mx = -1e30f;
        for (int ai = 0; ai < AD; ++ai) if (slog[ai] > mx) mx = slog[ai];
        float sum = 0.0f;
        float e[AD];
        for (int ai = 0; ai < AD; ++ai) { e[ai] = expf(slog[ai] - mx); sum += e[ai]; }
        float is = 1.0f / sum;
        for (int ai = 0; ai < AD; ++ai) out[ai] = e[ai] * is;
    }
}

// ---------- launch ----------
extern "C" void kernel_launch(void* const* d_in, const int* in_sizes, int n_in,
                              void* d_out, int out_size) {
    const float* state  = (const float*)d_in[0];  // 2^21 float32
    const float* params = (const float*)d_in[1];  // 252 float32
    const float* hw     = (const float*)d_in[2];  // 18*21 float32
    const float* hb     = (const float*)d_in[3];  // 18 float32
    float* out = (float*)d_out;

    pass_h<1, 1><<<512, 256>>>(params, state, 0);
    pass_l<<<512, 256>>>(params, 0);
    pass_h<0, 1><<<512, 256>>>(params, state, 1);
    pass_l<<<512, 256>>>(params, 1);
    pass_h<0, 1><<<512, 256>>>(params, state, 2);
    pass_l<<<512, 256>>>(params, 2);
    meas_hl<<<1024, 256>>>();
    head_kernel<<<1, 32>>>(params, hw, hb, out);
}